// round 8
// baseline (speedup 1.0000x reference)
#include <cuda_runtime.h>
#include <math.h>

#define PI_D 3.14159265358979323846

// ---------------- static device scratch ----------------
__device__ float4 g_S4[512 * 128 * 128];      // state [b][X][Y], float4 = (f0, f1) complex pair
__device__ float4 g_U0[128 * 128 * 2];        // mux0 unitaries, bitrev-permuted
__device__ float4 g_U1[2 * 2 * 64 * 64 * 2];
__device__ float4 g_U2[2 * 2 * 32 * 32 * 2];
__device__ float2 g_TW[64];                   // exp(-2*pi*i*t/128)
__device__ int    g_NR[128];                  // bitrev-domain negation table
__device__ float  g_part[512 * 2 * 10];       // partial logits per (b, xc1)

// ---- float2 complex helpers ----
__device__ __forceinline__ float2 cmul(float2 a, float2 b) {
    return make_float2(a.x * b.x - a.y * b.y, a.x * b.y + a.y * b.x);
}
__device__ __forceinline__ float2 f2add(float2 a, float2 b) { return make_float2(a.x + b.x, a.y + b.y); }
__device__ __forceinline__ float2 f2sub(float2 a, float2 b) { return make_float2(a.x - b.x, a.y - b.y); }
__device__ __forceinline__ float2 csq(float2 a) { return make_float2(a.x * a.x - a.y * a.y, 2.f * a.x * a.y); }

// ---- float4 = two complex numbers, same twiddle applied to both ----
__device__ __forceinline__ float4 f4add(float4 a, float4 b) {
    return make_float4(a.x + b.x, a.y + b.y, a.z + b.z, a.w + b.w);
}
__device__ __forceinline__ float4 f4sub(float4 a, float4 b) {
    return make_float4(a.x - b.x, a.y - b.y, a.z - b.z, a.w - b.w);
}
__device__ __forceinline__ float4 f4sc(float4 a, float s) {
    return make_float4(a.x * s, a.y * s, a.z * s, a.w * s);
}
__device__ __forceinline__ float4 c4mul(float4 v, float2 w) {
    return make_float4(v.x * w.x - v.y * w.y, v.x * w.y + v.y * w.x,
                       v.z * w.x - v.w * w.y, v.z * w.y + v.w * w.x);
}
__device__ __forceinline__ float4 c4mulc(float4 v, float2 w) {
    return make_float4(v.x * w.x + v.y * w.y, v.y * w.x - v.x * w.y,
                       v.z * w.x + v.w * w.y, v.w * w.x - v.z * w.y);
}
__device__ __forceinline__ float4 c4mulnegi(float4 v) {  // *( -i )
    return make_float4(v.y, -v.x, v.w, -v.z);
}
__device__ __forceinline__ float4 c4mulposi(float4 v) {  // *( +i )
    return make_float4(-v.y, v.x, -v.w, v.z);
}
// mux on one float4 site: q0=(x,y), q1=(z,w)
__device__ __forceinline__ float4 mux4(float4 v, float4 uA, float4 uB) {
    float4 o;
    o.x = uA.x * v.x - uA.y * v.y + uA.z * v.z - uA.w * v.w;
    o.y = uA.x * v.y + uA.y * v.x + uA.z * v.w + uA.w * v.z;
    o.z = uB.x * v.x - uB.y * v.y + uB.z * v.z - uB.w * v.w;
    o.w = uB.x * v.y + uB.y * v.x + uB.z * v.w + uB.w * v.z;
    return o;
}

// =====================================================================
// float4 FFT passes. element (line, p) at base[(line&(2^LG1-1))*SL1 + (line>>LG1)*SL2 + p*SP]
// FWD: DIF natural->bitrev; INV: DIT bitrev->natural (conj twiddles), scale on LAST.
// =====================================================================
template<bool INV, int NTT, int SP, int SL1, int LG1, int SL2, int LG2, int LOGN, int S, bool LAST>
__device__ __forceinline__ void pass4(float4* __restrict__ base,
                                      const float2* __restrict__ tw, float scale) {
    constexpr int L = 1 << (LG1 + LG2);
    constexpr int ITEMS = L << (LOGN - 2);
    constexpr int h = 1 << S;
    for (int u = threadIdx.x; u < ITEMS; u += NTT) {
        const int line = u & (L - 1);
        const int loff = (line & ((1 << LG1) - 1)) * SL1 + (line >> LG1) * SL2;
        const int v = u >> (LG1 + LG2);
        const int t = v & (h - 1);
        const int p = ((v >> S) << (S + 2)) + t;
        float4* e = base + loff + p * SP;
        float4 a = e[0], b = e[h * SP], c = e[2 * h * SP], d = e[3 * h * SP];
        const float2 w0 = tw[t << (5 - S)];
        const float2 w1 = make_float2(w0.y, -w0.x);
        const float2 w2 = csq(w0);
        if constexpr (!INV) {
            float4 ac = f4add(a, c), bd = f4add(b, d);
            float4 cP = c4mul(f4sub(a, c), w0);
            float4 dP = c4mul(f4sub(b, d), w1);
            e[0]          = f4add(ac, bd);
            e[h * SP]     = c4mul(f4sub(ac, bd), w2);
            e[2 * h * SP] = f4add(cP, dP);
            e[3 * h * SP] = c4mul(f4sub(cP, dP), w2);
        } else {
            float4 bw = c4mulc(b, w2), dw = c4mulc(d, w2);
            float4 aP = f4add(a, bw), bP = f4sub(a, bw);
            float4 cP = f4add(c, dw), dP = f4sub(c, dw);
            float4 cw = c4mulc(cP, w0), dq = c4mulc(dP, w1);
            float4 o0 = f4add(aP, cw), o2 = f4sub(aP, cw);
            float4 o1 = f4add(bP, dq), o3 = f4sub(bP, dq);
            if constexpr (LAST) {
                o0 = f4sc(o0, scale); o1 = f4sc(o1, scale);
                o2 = f4sc(o2, scale); o3 = f4sc(o3, scale);
            }
            e[0] = o0; e[h * SP] = o1; e[2 * h * SP] = o2; e[3 * h * SP] = o3;
        }
    }
    __syncthreads();
}

template<bool INV, int NTT, int SP, int SL1, int LG1, int SL2, int LG2, int LOGN, int S, bool LAST>
__device__ __forceinline__ void pass2(float4* __restrict__ base,
                                      const float2* __restrict__ tw, float scale) {
    constexpr int L = 1 << (LG1 + LG2);
    constexpr int ITEMS = L << (LOGN - 1);
    constexpr int h = 1 << S;
    for (int u = threadIdx.x; u < ITEMS; u += NTT) {
        const int line = u & (L - 1);
        const int loff = (line & ((1 << LG1) - 1)) * SL1 + (line >> LG1) * SL2;
        const int v = u >> (LG1 + LG2);
        const int t = v & (h - 1);
        const int p = ((v >> S) << (S + 1)) + t;
        float4* e = base + loff + p * SP;
        float4 a = e[0], b = e[h * SP];
        const float2 w = tw[t << (6 - S)];
        if constexpr (!INV) {
            e[0]      = f4add(a, b);
            e[h * SP] = c4mul(f4sub(a, b), w);
        } else {
            float4 bw = c4mulc(b, w);
            float4 o0 = f4add(a, bw), o1 = f4sub(a, bw);
            if constexpr (LAST) { o0 = f4sc(o0, scale); o1 = f4sc(o1, scale); }
            e[0] = o0; e[h * SP] = o1;
        }
    }
    __syncthreads();
}

template<bool INV, int NTT, int SP, int SL1, int LG1, int SL2, int LG2, int LOGN>
__device__ __forceinline__ void fft_run(float4* __restrict__ base,
                                        const float2* __restrict__ tw, float scale) {
    if constexpr (!INV) {
        if constexpr (LOGN == 6) {
            pass4<false, NTT, SP, SL1, LG1, SL2, LG2, 6, 4, false>(base, tw, 1.f);
            pass4<false, NTT, SP, SL1, LG1, SL2, LG2, 6, 2, false>(base, tw, 1.f);
            pass4<false, NTT, SP, SL1, LG1, SL2, LG2, 6, 0, false>(base, tw, 1.f);
        } else {
            pass4<false, NTT, SP, SL1, LG1, SL2, LG2, 5, 3, false>(base, tw, 1.f);
            pass4<false, NTT, SP, SL1, LG1, SL2, LG2, 5, 1, false>(base, tw, 1.f);
            pass2<false, NTT, SP, SL1, LG1, SL2, LG2, 5, 0, false>(base, tw, 1.f);
        }
    } else {
        if constexpr (LOGN == 6) {
            pass4<true, NTT, SP, SL1, LG1, SL2, LG2, 6, 0, false>(base, tw, 1.f);
            pass4<true, NTT, SP, SL1, LG1, SL2, LG2, 6, 2, false>(base, tw, 1.f);
            pass4<true, NTT, SP, SL1, LG1, SL2, LG2, 6, 4, true >(base, tw, scale);
        } else {
            pass4<true, NTT, SP, SL1, LG1, SL2, LG2, 5, 0, false>(base, tw, 1.f);
            pass4<true, NTT, SP, SL1, LG1, SL2, LG2, 5, 2, false>(base, tw, 1.f);
            pass2<true, NTT, SP, SL1, LG1, SL2, LG2, 5, 4, true >(base, tw, scale);
        }
    }
}

// ---------------- float2 passes (p1 only: packed Hermitian plane) ----------------
template<int NTT, int SP, int LG1, int LOGN, int S>
__device__ __forceinline__ void pass4s(float2* __restrict__ base,
                                       const float2* __restrict__ tw) {
    constexpr int L = 1 << LG1;
    constexpr int ITEMS = L << (LOGN - 2);
    constexpr int h = 1 << S;
    for (int u = threadIdx.x; u < ITEMS; u += NTT) {
        const int loff = (u & (L - 1));
        const int v = u >> LG1;
        const int t = v & (h - 1);
        const int p = ((v >> S) << (S + 2)) + t;
        float2* e = base + loff + p * SP;
        float2 a = e[0], b = e[h * SP], c = e[2 * h * SP], d = e[3 * h * SP];
        const float2 w0 = tw[t << (5 - S)];
        const float2 w1 = make_float2(w0.y, -w0.x);
        const float2 w2 = csq(w0);
        float2 ac = f2add(a, c), bd = f2add(b, d);
        float2 cP = cmul(f2sub(a, c), w0);
        float2 dP = cmul(f2sub(b, d), w1);
        e[0]          = f2add(ac, bd);
        e[h * SP]     = cmul(f2sub(ac, bd), w2);
        e[2 * h * SP] = f2add(cP, dP);
        e[3 * h * SP] = cmul(f2sub(cP, dP), w2);
    }
    __syncthreads();
}
template<int NTT, int SP, int LG1, int LOGN, int S>
__device__ __forceinline__ void pass2s(float2* __restrict__ base,
                                       const float2* __restrict__ tw) {
    constexpr int L = 1 << LG1;
    constexpr int ITEMS = L << (LOGN - 1);
    constexpr int h = 1 << S;
    for (int u = threadIdx.x; u < ITEMS; u += NTT) {
        const int loff = (u & (L - 1));
        const int v = u >> LG1;
        const int t = v & (h - 1);
        const int p = ((v >> S) << (S + 1)) + t;
        float2* e = base + loff + p * SP;
        float2 a = e[0], b = e[h * SP];
        const float2 w = tw[t << (6 - S)];
        e[0]      = f2add(a, b);
        e[h * SP] = cmul(f2sub(a, b), w);
    }
    __syncthreads();
}

// ---------------- K0: precompute ----------------
__device__ __forceinline__ void writeU(float4* dst, float axf, float ayf, float azf) {
    double ax = axf, ay = ayf, az = azf;
    double r = sqrt(ax * ax + ay * ay + az * az + 1e-20);
    double cr = cos(r), sn = sin(r) / r;
    dst[0] = make_float4((float)cr, (float)(-az * sn), (float)(-ay * sn), (float)(-ax * sn));
    dst[1] = make_float4((float)(ay * sn), (float)(-ax * sn), (float)cr, (float)(az * sn));
}

__global__ void k0(const float* __restrict__ mux0, const float* __restrict__ mux1,
                   const float* __restrict__ mux2) {
    int idx = blockIdx.x * blockDim.x + threadIdx.x;   // 16384 threads
    if (idx < 64) {
        double ang = -2.0 * PI_D * (double)idx / 128.0;
        g_TW[idx] = make_float2((float)cos(ang), (float)sin(ang));
    }
    if (idx < 128) {
        int k = __brev((unsigned)idx) >> 25;
        g_NR[idx] = (int)(__brev((unsigned)((128 - k) & 127)) >> 25);
    }
    {
        int kxb = idx >> 7, kyb = idx & 127;
        int kx = __brev((unsigned)kxb) >> 25, ky = __brev((unsigned)kyb) >> 25;
        const float* c = mux0 + (kx * 128 + ky) * 3;
        writeU(&g_U0[idx * 2], c[0], c[1], c[2]);
    }
    {
        int cx = idx >> 13, cy = (idx >> 12) & 1, kxb = (idx >> 6) & 63, kyb = idx & 63;
        int kx = __brev((unsigned)kxb) >> 26, ky = __brev((unsigned)kyb) >> 26;
        const float* c = mux1 + (((cx * 2 + cy) * 64 + kx) * 64 + ky) * 3;
        writeU(&g_U1[idx * 2], c[0], c[1], c[2]);
    }
    if (idx < 4096) {
        int cx = idx >> 11, cy = (idx >> 10) & 1, kxb = (idx >> 5) & 31, kyb = idx & 31;
        int kx = __brev((unsigned)kxb) >> 27, ky = __brev((unsigned)kyb) >> 27;
        const float* c = mux2 + (((cx * 2 + cy) * 32 + kx) * 32 + ky) * 3;
        writeU(&g_U2[idx * 2], c[0], c[1], c[2]);
    }
}

// ---------------- P1: encode + y-FFT128 (Hermitian packed) ----------------
#define NT1 512
__global__ __launch_bounds__(NT1) void p1(const float* __restrict__ images) {
    __shared__ float2 z[128 * 33];
    __shared__ float2 tw[64];
    const int b = blockIdx.y, X0 = blockIdx.x * 32;
    for (int i = threadIdx.x; i < 64; i += NT1) tw[i] = g_TW[i];
    for (int idx = threadIdx.x; idx < 4096; idx += NT1) {
        int l = idx >> 7, y = idx & 127;
        float I = images[(b * 128 + X0 + l) * 128 + y];
        float sv, cv;
        sincosf(0.5f * (float)PI_D * I, &sv, &cv);
        z[y * 33 + l] = make_float2(cv * (1.0f / 128.0f), sv * (1.0f / 128.0f));
    }
    __syncthreads();
    pass4s<NT1, 33, 5, 7, 5>(z, tw);
    pass4s<NT1, 33, 5, 7, 3>(z, tw);
    pass4s<NT1, 33, 5, 7, 1>(z, tw);
    pass2s<NT1, 33, 5, 7, 0>(z, tw);
    for (int idx = threadIdx.x; idx < 4096; idx += NT1) {
        int l = idx >> 7, kb = idx & 127;
        float2 Z = z[kb * 33 + l];
        float2 Zn = z[g_NR[kb] * 33 + l];
        float2 C  = make_float2(0.5f * (Z.x + Zn.x), 0.5f * (Z.y - Zn.y));
        float2 Sf = make_float2(0.5f * (Z.y + Zn.y), 0.5f * (Zn.x - Z.x));
        int X = X0 + l;
        g_S4[(b * 128 + X) * 128 + kb] = make_float4(C.x, C.y, Sf.x, Sf.y);
    }
}

// ---------------- P2: x-FFT128 + mux0 + x-IFFT128 + x-FFT64(halves) ----------------
#define NT2 512
__global__ __launch_bounds__(NT2) void p2() {
    __shared__ float4 tile[128 * 16];
    __shared__ float2 tw[64];
    const int b = blockIdx.y, y0 = blockIdx.x * 16;
    for (int i = threadIdx.x; i < 64; i += NT2) tw[i] = g_TW[i];
    __syncthreads();
    // fused: fwd7 pass4 S=5 reading directly from global
    for (int u = threadIdx.x; u < 512; u += NT2) {
        int yl = u & 15, v = u >> 4;                 // v in [0,32) = position
        const float4* g = &g_S4[(b * 128 + v) * 128 + y0 + yl];
        float4 a = g[0], bb = g[32 * 128], c = g[64 * 128], d = g[96 * 128];
        const float2 w0 = tw[v];
        const float2 w1 = make_float2(w0.y, -w0.x);
        const float2 w2 = csq(w0);
        float4 ac = f4add(a, c), bd = f4add(bb, d);
        float4 cP = c4mul(f4sub(a, c), w0);
        float4 dP = c4mul(f4sub(bb, d), w1);
        float4* e = tile + v * 16 + yl;
        e[0]       = f4add(ac, bd);
        e[32 * 16] = c4mul(f4sub(ac, bd), w2);
        e[64 * 16] = f4add(cP, dP);
        e[96 * 16] = c4mul(f4sub(cP, dP), w2);
    }
    __syncthreads();
    pass4<false, NT2, 16, 1, 4, 0, 0, 7, 3, false>(tile, tw, 1.f);
    pass4<false, NT2, 16, 1, 4, 0, 0, 7, 1, false>(tile, tw, 1.f);
    // fused: fwd7 pass2 S=0 (w=1) + mux0
    for (int u = threadIdx.x; u < 1024; u += NT2) {
        int yl = u & 15, v = u >> 4;                 // v in [0,64)
        float4* e = tile + (2 * v) * 16 + yl;
        float4 a = e[0], bb = e[16];
        float4 o0 = f4add(a, bb), o1 = f4sub(a, bb);
        int i0 = (((2 * v) << 7) + y0 + yl) * 2;
        int i1 = (((2 * v + 1) << 7) + y0 + yl) * 2;
        e[0]  = mux4(o0, g_U0[i0], g_U0[i0 + 1]);
        e[16] = mux4(o1, g_U0[i1], g_U0[i1 + 1]);
    }
    __syncthreads();
    // inv128
    pass4<true, NT2, 16, 1, 4, 0, 0, 7, 0, false>(tile, tw, 1.f);
    pass4<true, NT2, 16, 1, 4, 0, 0, 7, 2, false>(tile, tw, 1.f);
    pass4<true, NT2, 16, 1, 4, 0, 0, 7, 4, false>(tile, tw, 1.f);
    pass2<true, NT2, 16, 1, 4, 0, 0, 7, 6, true >(tile, tw, 1.0f / 128.0f);
    // fwd64 halves: S=4, S=2, then fused S=0 + global store
    pass4<false, NT2, 16, 1, 4, 1024, 1, 6, 4, false>(tile, tw, 1.f);
    pass4<false, NT2, 16, 1, 4, 1024, 1, 6, 2, false>(tile, tw, 1.f);
    for (int u = threadIdx.x; u < 512; u += NT2) {
        int yl = u & 15, half = (u >> 4) & 1, v = u >> 5;   // v in [0,16)
        float4* e = tile + half * 1024 + (4 * v) * 16 + yl;
        float4 a = e[0], bb = e[16], c = e[32], d = e[48];
        // t=0: w0=1, w1=-i, w2=1
        float4 ac = f4add(a, c), bd = f4add(bb, d);
        float4 cP = f4sub(a, c);
        float4 dP = c4mulnegi(f4sub(bb, d));
        int Xb = half * 64 + 4 * v;
        float4* g = &g_S4[(b * 128 + Xb) * 128 + y0 + yl];
        g[0]   = f4add(ac, bd);
        g[128] = f4sub(ac, bd);
        g[256] = f4add(cP, dP);
        g[384] = f4sub(cP, dP);
    }
}

// ---------------- P35: y-junction(mux1 fused) + x-junction + y-junction(mux2 fused)
//                   + final IFFT32s + measure + partial GEMV ----------------
#define NT3 1024
#define P35_SMEM (132096 + 512 + 8192 + 1280)
__global__ __launch_bounds__(NT3) void p35(const float* __restrict__ W) {
    extern __shared__ char sm[];
    float4* tile = (float4*)sm;                            // [64 X][129] float4
    float2* tw   = (float2*)(sm + 132096);
    float*  prob = (float*)(sm + 132096 + 512);            // 2048 f32
    float*  red  = (float*)(sm + 132096 + 512 + 8192);     // 32*10 f32
    const int b = blockIdx.y, xc1 = blockIdx.x;
    for (int i = threadIdx.x; i < 64; i += NT3) tw[i] = g_TW[i];
    __syncthreads();
    // fused: inv7-y pass4 S=0 reading directly from global (t=0: w0=1, w1=-i -> conj=+i, w2=1)
    for (int u = threadIdx.x; u < 2048; u += NT3) {
        int X = u & 63, v = u >> 6;                        // v in [0,32)
        const float4* g = &g_S4[(b * 128 + xc1 * 64 + X) * 128 + 4 * v];
        float4 a = g[0], bb = g[1], c = g[2], d = g[3];
        float4 aP = f4add(a, bb), bP = f4sub(a, bb);
        float4 cP = f4add(c, d);
        float4 dq = c4mulposi(f4sub(c, d));
        float4* e = tile + X * 129 + 4 * v;
        e[0] = f4add(aP, cP);
        e[2] = f4sub(aP, cP);
        e[1] = f4add(bP, dq);
        e[3] = f4sub(bP, dq);
    }
    __syncthreads();
    pass4<true, NT3, 1, 129, 6, 0, 0, 7, 2, false>(tile, tw, 1.f);
    pass4<true, NT3, 1, 129, 6, 0, 0, 7, 4, false>(tile, tw, 1.f);
    pass2<true, NT3, 1, 129, 6, 0, 0, 7, 6, true >(tile, tw, 1.0f / 128.0f);
    // fwd64 y halves: S=4, S=2, fused S=0 + mux1
    pass4<false, NT3, 1, 129, 6, 64, 1, 6, 4, false>(tile, tw, 1.f);
    pass4<false, NT3, 1, 129, 6, 64, 1, 6, 2, false>(tile, tw, 1.f);
    for (int u = threadIdx.x; u < 2048; u += NT3) {
        int X = u & 63, half = (u >> 6) & 1, v = u >> 7;   // v in [0,16)
        float4* e = tile + X * 129 + half * 64 + 4 * v;
        float4 a = e[0], bb = e[1], c = e[2], d = e[3];
        // t=0: w0=1, w1=-i, w2=1
        float4 ac = f4add(a, c), bd = f4add(bb, d);
        float4 cP = f4sub(a, c);
        float4 dP = c4mulnegi(f4sub(bb, d));
        float4 o0 = f4add(ac, bd), o1 = f4sub(ac, bd);
        float4 o2 = f4add(cP, dP), o3 = f4sub(cP, dP);
        int ub = ((((xc1 * 2 + half) << 12) + (X << 6) + 4 * v)) * 2;
        e[0] = mux4(o0, g_U1[ub],     g_U1[ub + 1]);
        e[1] = mux4(o1, g_U1[ub + 2], g_U1[ub + 3]);
        e[2] = mux4(o2, g_U1[ub + 4], g_U1[ub + 5]);
        e[3] = mux4(o3, g_U1[ub + 6], g_U1[ub + 7]);
    }
    __syncthreads();
    // x junction 64->32
    fft_run<true,  NT3, 129, 1, 7, 0,    0, 6>(tile, tw, 1.0f / 64.0f);
    fft_run<false, NT3, 129, 1, 7, 4128, 1, 5>(tile, tw, 1.f);
    // y junction 64->32: inv64 halves, fwd32 segs (S=3, S=1, fused S=0 + mux2)
    fft_run<true, NT3, 1, 129, 6, 64, 1, 6>(tile, tw, 1.0f / 64.0f);
    pass4<false, NT3, 1, 129, 6, 32, 2, 5, 3, false>(tile, tw, 1.f);
    pass4<false, NT3, 1, 129, 6, 32, 2, 5, 1, false>(tile, tw, 1.f);
    for (int u = threadIdx.x; u < 4096; u += NT3) {
        int X = u & 63, seg = (u >> 6) & 3, v = u >> 8;    // v in [0,16)
        float4* e = tile + X * 129 + seg * 32 + 2 * v;
        float4 a = e[0], bb = e[1];
        float4 o0 = f4add(a, bb), o1 = f4sub(a, bb);       // w=1
        int xc2 = X >> 5, yc2 = seg & 1;
        int ub = ((((xc2 * 2 + yc2) << 10) + ((X & 31) << 5) + 2 * v)) * 2;
        e[0] = mux4(o0, g_U2[ub],     g_U2[ub + 1]);
        e[1] = mux4(o1, g_U2[ub + 2], g_U2[ub + 3]);
    }
    __syncthreads();
    // final iqft2d (32-point both axes)
    fft_run<true, NT3, 129, 1, 7, 4128, 1, 5>(tile, tw, 1.0f / 32.0f);
    fft_run<true, NT3, 1, 129, 6, 32,   2, 5>(tile, tw, 1.0f / 32.0f);
    // measurement: partial prob over (xc2, yc1, yc2)
    for (int idx = threadIdx.x; idx < 1024; idx += NT3) {
        int ya = idx & 31, xa = idx >> 5;
        float s0 = 0.f, s1 = 0.f;
        #pragma unroll
        for (int xc2 = 0; xc2 < 2; ++xc2)
            #pragma unroll
            for (int yq = 0; yq < 4; ++yq) {
                float4 v = tile[(xc2 * 32 + xa) * 129 + yq * 32 + ya];
                s0 += v.x * v.x + v.y * v.y;
                s1 += v.z * v.z + v.w * v.w;
            }
        prob[(xa * 32 + ya) * 2 + 0] = s0;
        prob[(xa * 32 + ya) * 2 + 1] = s1;
    }
    __syncthreads();
    // partial GEMV
    float acc[10];
    #pragma unroll
    for (int c = 0; c < 10; ++c) acc[c] = 0.f;
    {
        int j0 = threadIdx.x * 2;
        float2 pv = *(const float2*)(prob + j0);
        #pragma unroll
        for (int c = 0; c < 10; ++c) {
            float2 wv = *(const float2*)(W + c * 2048 + j0);
            acc[c] = fmaf(pv.x, wv.x, fmaf(pv.y, wv.y, acc[c]));
        }
    }
    #pragma unroll
    for (int c = 0; c < 10; ++c)
        #pragma unroll
        for (int o = 16; o > 0; o >>= 1)
            acc[c] += __shfl_down_sync(0xffffffffu, acc[c], o);
    const int warp = threadIdx.x >> 5, lane = threadIdx.x & 31;
    if (lane == 0)
        #pragma unroll
        for (int c = 0; c < 10; ++c) red[warp * 10 + c] = acc[c];
    __syncthreads();
    if (threadIdx.x < 10) {
        float s = 0.f;
        #pragma unroll
        for (int w = 0; w < 32; ++w) s += red[w * 10 + threadIdx.x];
        g_part[(b * 2 + xc1) * 10 + threadIdx.x] = s;
    }
}

// ---------------- combine ----------------
__global__ void pc(const float* __restrict__ bias, float* __restrict__ out) {
    int i = blockIdx.x * blockDim.x + threadIdx.x;
    if (i < 5120) {
        int b = i / 10, c = i % 10;
        out[i] = bias[c] + g_part[(b * 2) * 10 + c] + g_part[(b * 2 + 1) * 10 + c];
    }
}

// ---------------- launch ----------------
extern "C" void kernel_launch(void* const* d_in, const int* in_sizes, int n_in,
                              void* d_out, int out_size) {
    const float* images = (const float*)d_in[0];
    const float* mux0 = (const float*)d_in[1];
    const float* mux1 = (const float*)d_in[2];
    const float* mux2 = (const float*)d_in[3];
    const float* W = (const float*)d_in[4];
    const float* bias = (const float*)d_in[5];
    float* out = (float*)d_out;
    (void)in_sizes; (void)n_in; (void)out_size;

    cudaFuncSetAttribute(p35, cudaFuncAttributeMaxDynamicSharedMemorySize, P35_SMEM);

    k0<<<64, 256>>>(mux0, mux1, mux2);
    p1<<<dim3(4, 512), NT1>>>(images);
    p2<<<dim3(8, 512), NT2>>>();
    p35<<<dim3(2, 512), NT3, P35_SMEM>>>(W);
    pc<<<10, 512>>>(bias, out);
}

// round 10
// speedup vs baseline: 1.1933x; 1.1933x over previous
#include <cuda_runtime.h>
#include <math.h>

#define PI_D 3.14159265358979323846

// ---------------- static device scratch ----------------
__device__ float4 g_S4[512 * 128 * 128];      // state [b][X][Y], float4 = (f0, f1) complex pair
__device__ float4 g_U0[128 * 128 * 2];        // mux0, bitrev-permuted, [kxb][kyb]
__device__ float4 g_U1[2 * 2 * 64 * 64 * 2];  // mux1, bitrev-permuted, TRANSPOSED [cx][cy][kyb][kxb]
__device__ float4 g_U2[2 * 2 * 32 * 32 * 2];  // mux2, bitrev-permuted, TRANSPOSED [cx][cy][kyb][kxb]
__device__ float2 g_TW[64];                   // exp(-2*pi*i*t/128)
__device__ int    g_NR[128];                  // bitrev-domain negation table
__device__ float  g_part[512 * 2 * 10];       // partial logits per (b, xc1)

// ---- float2 complex helpers ----
__device__ __forceinline__ float2 cmul(float2 a, float2 b) {
    return make_float2(a.x * b.x - a.y * b.y, a.x * b.y + a.y * b.x);
}
__device__ __forceinline__ float2 f2add(float2 a, float2 b) { return make_float2(a.x + b.x, a.y + b.y); }
__device__ __forceinline__ float2 f2sub(float2 a, float2 b) { return make_float2(a.x - b.x, a.y - b.y); }
__device__ __forceinline__ float2 csq(float2 a) { return make_float2(a.x * a.x - a.y * a.y, 2.f * a.x * a.y); }

// ---- float4 = two complex numbers, same twiddle applied to both ----
__device__ __forceinline__ float4 f4add(float4 a, float4 b) {
    return make_float4(a.x + b.x, a.y + b.y, a.z + b.z, a.w + b.w);
}
__device__ __forceinline__ float4 f4sub(float4 a, float4 b) {
    return make_float4(a.x - b.x, a.y - b.y, a.z - b.z, a.w - b.w);
}
__device__ __forceinline__ float4 f4sc(float4 a, float s) {
    return make_float4(a.x * s, a.y * s, a.z * s, a.w * s);
}
__device__ __forceinline__ float4 c4mul(float4 v, float2 w) {
    return make_float4(v.x * w.x - v.y * w.y, v.x * w.y + v.y * w.x,
                       v.z * w.x - v.w * w.y, v.z * w.y + v.w * w.x);
}
__device__ __forceinline__ float4 c4mulc(float4 v, float2 w) {
    return make_float4(v.x * w.x + v.y * w.y, v.y * w.x - v.x * w.y,
                       v.z * w.x + v.w * w.y, v.w * w.x - v.z * w.y);
}
__device__ __forceinline__ float4 c4mulnegi(float4 v) {  // *( -i )
    return make_float4(v.y, -v.x, v.w, -v.z);
}
__device__ __forceinline__ float4 c4mulposi(float4 v) {  // *( +i )
    return make_float4(-v.y, v.x, -v.w, v.z);
}
// mux on one float4 site: q0=(x,y), q1=(z,w)
__device__ __forceinline__ float4 mux4(float4 v, float4 uA, float4 uB) {
    float4 o;
    o.x = uA.x * v.x - uA.y * v.y + uA.z * v.z - uA.w * v.w;
    o.y = uA.x * v.y + uA.y * v.x + uA.z * v.w + uA.w * v.z;
    o.z = uB.x * v.x - uB.y * v.y + uB.z * v.z - uB.w * v.w;
    o.w = uB.x * v.y + uB.y * v.x + uB.z * v.w + uB.w * v.z;
    return o;
}

// =====================================================================
// float4 FFT passes. element (line, p) at base[(line&(2^LG1-1))*SL1 + (line>>LG1)*SL2 + p*SP]
// FWD: DIF natural->bitrev; INV: DIT bitrev->natural (conj twiddles), scale on LAST.
// =====================================================================
template<bool INV, int NTT, int SP, int SL1, int LG1, int SL2, int LG2, int LOGN, int S, bool LAST>
__device__ __forceinline__ void pass4(float4* __restrict__ base,
                                      const float2* __restrict__ tw, float scale) {
    constexpr int L = 1 << (LG1 + LG2);
    constexpr int ITEMS = L << (LOGN - 2);
    constexpr int h = 1 << S;
    for (int u = threadIdx.x; u < ITEMS; u += NTT) {
        const int line = u & (L - 1);
        const int loff = (line & ((1 << LG1) - 1)) * SL1 + (line >> LG1) * SL2;
        const int v = u >> (LG1 + LG2);
        const int t = v & (h - 1);
        const int p = ((v >> S) << (S + 2)) + t;
        float4* e = base + loff + p * SP;
        float4 a = e[0], b = e[h * SP], c = e[2 * h * SP], d = e[3 * h * SP];
        const float2 w0 = tw[t << (5 - S)];
        const float2 w1 = make_float2(w0.y, -w0.x);
        const float2 w2 = csq(w0);
        if constexpr (!INV) {
            float4 ac = f4add(a, c), bd = f4add(b, d);
            float4 cP = c4mul(f4sub(a, c), w0);
            float4 dP = c4mul(f4sub(b, d), w1);
            e[0]          = f4add(ac, bd);
            e[h * SP]     = c4mul(f4sub(ac, bd), w2);
            e[2 * h * SP] = f4add(cP, dP);
            e[3 * h * SP] = c4mul(f4sub(cP, dP), w2);
        } else {
            float4 bw = c4mulc(b, w2), dw = c4mulc(d, w2);
            float4 aP = f4add(a, bw), bP = f4sub(a, bw);
            float4 cP = f4add(c, dw), dP = f4sub(c, dw);
            float4 cw = c4mulc(cP, w0), dq = c4mulc(dP, w1);
            float4 o0 = f4add(aP, cw), o2 = f4sub(aP, cw);
            float4 o1 = f4add(bP, dq), o3 = f4sub(bP, dq);
            if constexpr (LAST) {
                o0 = f4sc(o0, scale); o1 = f4sc(o1, scale);
                o2 = f4sc(o2, scale); o3 = f4sc(o3, scale);
            }
            e[0] = o0; e[h * SP] = o1; e[2 * h * SP] = o2; e[3 * h * SP] = o3;
        }
    }
    __syncthreads();
}

template<bool INV, int NTT, int SP, int SL1, int LG1, int SL2, int LG2, int LOGN, int S, bool LAST>
__device__ __forceinline__ void pass2(float4* __restrict__ base,
                                      const float2* __restrict__ tw, float scale) {
    constexpr int L = 1 << (LG1 + LG2);
    constexpr int ITEMS = L << (LOGN - 1);
    constexpr int h = 1 << S;
    for (int u = threadIdx.x; u < ITEMS; u += NTT) {
        const int line = u & (L - 1);
        const int loff = (line & ((1 << LG1) - 1)) * SL1 + (line >> LG1) * SL2;
        const int v = u >> (LG1 + LG2);
        const int t = v & (h - 1);
        const int p = ((v >> S) << (S + 1)) + t;
        float4* e = base + loff + p * SP;
        float4 a = e[0], b = e[h * SP];
        const float2 w = tw[t << (6 - S)];
        if constexpr (!INV) {
            e[0]      = f4add(a, b);
            e[h * SP] = c4mul(f4sub(a, b), w);
        } else {
            float4 bw = c4mulc(b, w);
            float4 o0 = f4add(a, bw), o1 = f4sub(a, bw);
            if constexpr (LAST) { o0 = f4sc(o0, scale); o1 = f4sc(o1, scale); }
            e[0] = o0; e[h * SP] = o1;
        }
    }
    __syncthreads();
}

template<bool INV, int NTT, int SP, int SL1, int LG1, int SL2, int LG2, int LOGN>
__device__ __forceinline__ void fft_run(float4* __restrict__ base,
                                        const float2* __restrict__ tw, float scale) {
    if constexpr (!INV) {
        if constexpr (LOGN == 6) {
            pass4<false, NTT, SP, SL1, LG1, SL2, LG2, 6, 4, false>(base, tw, 1.f);
            pass4<false, NTT, SP, SL1, LG1, SL2, LG2, 6, 2, false>(base, tw, 1.f);
            pass4<false, NTT, SP, SL1, LG1, SL2, LG2, 6, 0, false>(base, tw, 1.f);
        } else {
            pass4<false, NTT, SP, SL1, LG1, SL2, LG2, 5, 3, false>(base, tw, 1.f);
            pass4<false, NTT, SP, SL1, LG1, SL2, LG2, 5, 1, false>(base, tw, 1.f);
            pass2<false, NTT, SP, SL1, LG1, SL2, LG2, 5, 0, false>(base, tw, 1.f);
        }
    } else {
        if constexpr (LOGN == 6) {
            pass4<true, NTT, SP, SL1, LG1, SL2, LG2, 6, 0, false>(base, tw, 1.f);
            pass4<true, NTT, SP, SL1, LG1, SL2, LG2, 6, 2, false>(base, tw, 1.f);
            pass4<true, NTT, SP, SL1, LG1, SL2, LG2, 6, 4, true >(base, tw, scale);
        } else {
            pass4<true, NTT, SP, SL1, LG1, SL2, LG2, 5, 0, false>(base, tw, 1.f);
            pass4<true, NTT, SP, SL1, LG1, SL2, LG2, 5, 2, false>(base, tw, 1.f);
            pass2<true, NTT, SP, SL1, LG1, SL2, LG2, 5, 4, true >(base, tw, scale);
        }
    }
}

// ---------------- float2 passes (p1 only: packed Hermitian plane) ----------------
template<int NTT, int SP, int LG1, int LOGN, int S>
__device__ __forceinline__ void pass4s(float2* __restrict__ base,
                                       const float2* __restrict__ tw) {
    constexpr int L = 1 << LG1;
    constexpr int ITEMS = L << (LOGN - 2);
    constexpr int h = 1 << S;
    for (int u = threadIdx.x; u < ITEMS; u += NTT) {
        const int loff = (u & (L - 1));
        const int v = u >> LG1;
        const int t = v & (h - 1);
        const int p = ((v >> S) << (S + 2)) + t;
        float2* e = base + loff + p * SP;
        float2 a = e[0], b = e[h * SP], c = e[2 * h * SP], d = e[3 * h * SP];
        const float2 w0 = tw[t << (5 - S)];
        const float2 w1 = make_float2(w0.y, -w0.x);
        const float2 w2 = csq(w0);
        float2 ac = f2add(a, c), bd = f2add(b, d);
        float2 cP = cmul(f2sub(a, c), w0);
        float2 dP = cmul(f2sub(b, d), w1);
        e[0]          = f2add(ac, bd);
        e[h * SP]     = cmul(f2sub(ac, bd), w2);
        e[2 * h * SP] = f2add(cP, dP);
        e[3 * h * SP] = cmul(f2sub(cP, dP), w2);
    }
    __syncthreads();
}
template<int NTT, int SP, int LG1, int LOGN, int S>
__device__ __forceinline__ void pass2s(float2* __restrict__ base,
                                       const float2* __restrict__ tw) {
    constexpr int L = 1 << LG1;
    constexpr int ITEMS = L << (LOGN - 1);
    constexpr int h = 1 << S;
    for (int u = threadIdx.x; u < ITEMS; u += NTT) {
        const int loff = (u & (L - 1));
        const int v = u >> LG1;
        const int t = v & (h - 1);
        const int p = ((v >> S) << (S + 1)) + t;
        float2* e = base + loff + p * SP;
        float2 a = e[0], b = e[h * SP];
        const float2 w = tw[t << (6 - S)];
        e[0]      = f2add(a, b);
        e[h * SP] = cmul(f2sub(a, b), w);
    }
    __syncthreads();
}

// ---------------- K0: precompute ----------------
__device__ __forceinline__ void writeU(float4* dst, float axf, float ayf, float azf) {
    double ax = axf, ay = ayf, az = azf;
    double r = sqrt(ax * ax + ay * ay + az * az + 1e-20);
    double cr = cos(r), sn = sin(r) / r;
    dst[0] = make_float4((float)cr, (float)(-az * sn), (float)(-ay * sn), (float)(-ax * sn));
    dst[1] = make_float4((float)(ay * sn), (float)(-ax * sn), (float)cr, (float)(az * sn));
}

__global__ void k0(const float* __restrict__ mux0, const float* __restrict__ mux1,
                   const float* __restrict__ mux2) {
    int idx = blockIdx.x * blockDim.x + threadIdx.x;   // 16384 threads
    if (idx < 64) {
        double ang = -2.0 * PI_D * (double)idx / 128.0;
        g_TW[idx] = make_float2((float)cos(ang), (float)sin(ang));
    }
    if (idx < 128) {
        int k = __brev((unsigned)idx) >> 25;
        g_NR[idx] = (int)(__brev((unsigned)((128 - k) & 127)) >> 25);
    }
    {   // U0: [kxb][kyb] (consumed by p2 with Y-fastest lanes -> already coalesced)
        int kxb = idx >> 7, kyb = idx & 127;
        int kx = __brev((unsigned)kxb) >> 25, ky = __brev((unsigned)kyb) >> 25;
        const float* c = mux0 + (kx * 128 + ky) * 3;
        writeU(&g_U0[idx * 2], c[0], c[1], c[2]);
    }
    {   // U1: TRANSPOSED [cx][cy][kyb][kxb] (consumed by p35 with X-fastest lanes)
        int cx = idx >> 13, cy = (idx >> 12) & 1, kxb = (idx >> 6) & 63, kyb = idx & 63;
        int kx = __brev((unsigned)kxb) >> 26, ky = __brev((unsigned)kyb) >> 26;
        const float* c = mux1 + (((cx * 2 + cy) * 64 + kx) * 64 + ky) * 3;
        int tidx = (cx << 13) + (cy << 12) + (kyb << 6) + kxb;
        writeU(&g_U1[tidx * 2], c[0], c[1], c[2]);
    }
    if (idx < 4096) {   // U2: TRANSPOSED [cx][cy][kyb][kxb]
        int cx = idx >> 11, cy = (idx >> 10) & 1, kxb = (idx >> 5) & 31, kyb = idx & 31;
        int kx = __brev((unsigned)kxb) >> 27, ky = __brev((unsigned)kyb) >> 27;
        const float* c = mux2 + (((cx * 2 + cy) * 32 + kx) * 32 + ky) * 3;
        int tidx = (cx << 11) + (cy << 10) + (kyb << 5) + kxb;
        writeU(&g_U2[tidx * 2], c[0], c[1], c[2]);
    }
}

// ---------------- P1: encode + y-FFT128 (Hermitian packed) ----------------
#define NT1 512
__global__ __launch_bounds__(NT1) void p1(const float* __restrict__ images) {
    __shared__ float2 z[128 * 33];
    __shared__ float2 tw[64];
    const int b = blockIdx.y, X0 = blockIdx.x * 32;
    for (int i = threadIdx.x; i < 64; i += NT1) tw[i] = g_TW[i];
    for (int idx = threadIdx.x; idx < 4096; idx += NT1) {
        int l = idx >> 7, y = idx & 127;
        float I = images[(b * 128 + X0 + l) * 128 + y];
        float sv, cv;
        sincosf(0.5f * (float)PI_D * I, &sv, &cv);
        z[y * 33 + l] = make_float2(cv * (1.0f / 128.0f), sv * (1.0f / 128.0f));
    }
    __syncthreads();
    pass4s<NT1, 33, 5, 7, 5>(z, tw);
    pass4s<NT1, 33, 5, 7, 3>(z, tw);
    pass4s<NT1, 33, 5, 7, 1>(z, tw);
    pass2s<NT1, 33, 5, 7, 0>(z, tw);
    for (int idx = threadIdx.x; idx < 4096; idx += NT1) {
        int l = idx >> 7, kb = idx & 127;
        float2 Z = z[kb * 33 + l];
        float2 Zn = z[g_NR[kb] * 33 + l];
        float2 C  = make_float2(0.5f * (Z.x + Zn.x), 0.5f * (Z.y - Zn.y));
        float2 Sf = make_float2(0.5f * (Z.y + Zn.y), 0.5f * (Zn.x - Z.x));
        int X = X0 + l;
        g_S4[(b * 128 + X) * 128 + kb] = make_float4(C.x, C.y, Sf.x, Sf.y);
    }
}

// ---------------- P2: x-FFT128 + mux0 + x-IFFT128 + x-FFT64(halves) ----------------
#define NT2 512
__global__ __launch_bounds__(NT2) void p2() {
    __shared__ float4 tile[128 * 16];
    __shared__ float2 tw[64];
    const int b = blockIdx.y, y0 = blockIdx.x * 16;
    for (int i = threadIdx.x; i < 64; i += NT2) tw[i] = g_TW[i];
    __syncthreads();
    // fused: fwd7 pass4 S=5 reading directly from global
    for (int u = threadIdx.x; u < 512; u += NT2) {
        int yl = u & 15, v = u >> 4;                 // v in [0,32) = position
        const float4* g = &g_S4[(b * 128 + v) * 128 + y0 + yl];
        float4 a = g[0], bb = g[32 * 128], c = g[64 * 128], d = g[96 * 128];
        const float2 w0 = tw[v];
        const float2 w1 = make_float2(w0.y, -w0.x);
        const float2 w2 = csq(w0);
        float4 ac = f4add(a, c), bd = f4add(bb, d);
        float4 cP = c4mul(f4sub(a, c), w0);
        float4 dP = c4mul(f4sub(bb, d), w1);
        float4* e = tile + v * 16 + yl;
        e[0]       = f4add(ac, bd);
        e[32 * 16] = c4mul(f4sub(ac, bd), w2);
        e[64 * 16] = f4add(cP, dP);
        e[96 * 16] = c4mul(f4sub(cP, dP), w2);
    }
    __syncthreads();
    pass4<false, NT2, 16, 1, 4, 0, 0, 7, 3, false>(tile, tw, 1.f);
    pass4<false, NT2, 16, 1, 4, 0, 0, 7, 1, false>(tile, tw, 1.f);
    // fused: fwd7 pass2 S=0 (w=1) + mux0
    for (int u = threadIdx.x; u < 1024; u += NT2) {
        int yl = u & 15, v = u >> 4;                 // v in [0,64)
        float4* e = tile + (2 * v) * 16 + yl;
        float4 a = e[0], bb = e[16];
        float4 o0 = f4add(a, bb), o1 = f4sub(a, bb);
        int i0 = (((2 * v) << 7) + y0 + yl) * 2;
        int i1 = (((2 * v + 1) << 7) + y0 + yl) * 2;
        e[0]  = mux4(o0, g_U0[i0], g_U0[i0 + 1]);
        e[16] = mux4(o1, g_U0[i1], g_U0[i1 + 1]);
    }
    __syncthreads();
    // inv128
    pass4<true, NT2, 16, 1, 4, 0, 0, 7, 0, false>(tile, tw, 1.f);
    pass4<true, NT2, 16, 1, 4, 0, 0, 7, 2, false>(tile, tw, 1.f);
    pass4<true, NT2, 16, 1, 4, 0, 0, 7, 4, false>(tile, tw, 1.f);
    pass2<true, NT2, 16, 1, 4, 0, 0, 7, 6, true >(tile, tw, 1.0f / 128.0f);
    // fwd64 halves: S=4, S=2, then fused S=0 + global store
    pass4<false, NT2, 16, 1, 4, 1024, 1, 6, 4, false>(tile, tw, 1.f);
    pass4<false, NT2, 16, 1, 4, 1024, 1, 6, 2, false>(tile, tw, 1.f);
    for (int u = threadIdx.x; u < 512; u += NT2) {
        int yl = u & 15, half = (u >> 4) & 1, v = u >> 5;   // v in [0,16)
        float4* e = tile + half * 1024 + (4 * v) * 16 + yl;
        float4 a = e[0], bb = e[16], c = e[32], d = e[48];
        // t=0: w0=1, w1=-i, w2=1
        float4 ac = f4add(a, c), bd = f4add(bb, d);
        float4 cP = f4sub(a, c);
        float4 dP = c4mulnegi(f4sub(bb, d));
        int Xb = half * 64 + 4 * v;
        float4* g = &g_S4[(b * 128 + Xb) * 128 + y0 + yl];
        g[0]   = f4add(ac, bd);
        g[128] = f4sub(ac, bd);
        g[256] = f4add(cP, dP);
        g[384] = f4sub(cP, dP);
    }
}

// ---------------- P35: y-junction(mux1 fused) + x-junction + y-junction(mux2 fused)
//                   + final IFFT32s + measure + partial GEMV ----------------
#define NT3 1024
#define P35_SMEM (132096 + 512 + 8192 + 1280)
__global__ __launch_bounds__(NT3) void p35(const float* __restrict__ W) {
    extern __shared__ char sm[];
    float4* tile = (float4*)sm;                            // [64 X][129] float4
    float2* tw   = (float2*)(sm + 132096);
    float*  prob = (float*)(sm + 132096 + 512);            // 2048 f32
    float*  red  = (float*)(sm + 132096 + 512 + 8192);     // 32*10 f32
    const int b = blockIdx.y, xc1 = blockIdx.x;
    for (int i = threadIdx.x; i < 64; i += NT3) tw[i] = g_TW[i];
    __syncthreads();
    // fused: inv7-y pass4 S=0 reading directly from global (t=0: w0=1, w1=-i -> conj=+i, w2=1)
    for (int u = threadIdx.x; u < 2048; u += NT3) {
        int X = u & 63, v = u >> 6;                        // v in [0,32)
        const float4* g = &g_S4[(b * 128 + xc1 * 64 + X) * 128 + 4 * v];
        float4 a = g[0], bb = g[1], c = g[2], d = g[3];
        float4 aP = f4add(a, bb), bP = f4sub(a, bb);
        float4 cP = f4add(c, d);
        float4 dq = c4mulposi(f4sub(c, d));
        float4* e = tile + X * 129 + 4 * v;
        e[0] = f4add(aP, cP);
        e[2] = f4sub(aP, cP);
        e[1] = f4add(bP, dq);
        e[3] = f4sub(bP, dq);
    }
    __syncthreads();
    pass4<true, NT3, 1, 129, 6, 0, 0, 7, 2, false>(tile, tw, 1.f);
    pass4<true, NT3, 1, 129, 6, 0, 0, 7, 4, false>(tile, tw, 1.f);
    pass2<true, NT3, 1, 129, 6, 0, 0, 7, 6, true >(tile, tw, 1.0f / 128.0f);
    // fwd64 y halves: S=4, S=2, fused S=0 + mux1 (transposed table: coalesced in X)
    pass4<false, NT3, 1, 129, 6, 64, 1, 6, 4, false>(tile, tw, 1.f);
    pass4<false, NT3, 1, 129, 6, 64, 1, 6, 2, false>(tile, tw, 1.f);
    for (int u = threadIdx.x; u < 2048; u += NT3) {
        int X = u & 63, half = (u >> 6) & 1, v = u >> 7;   // v in [0,16)
        float4* e = tile + X * 129 + half * 64 + 4 * v;
        float4 a = e[0], bb = e[1], c = e[2], d = e[3];
        // t=0: w0=1, w1=-i, w2=1
        float4 ac = f4add(a, c), bd = f4add(bb, d);
        float4 cP = f4sub(a, c);
        float4 dP = c4mulnegi(f4sub(bb, d));
        float4 o0 = f4add(ac, bd), o1 = f4sub(ac, bd);
        float4 o2 = f4add(cP, dP), o3 = f4sub(cP, dP);
        // transposed U1: index = ((cx*2+cy)<<12) + (Yb<<6) + X, Yb = 4v+k
        int ub = (((xc1 * 2 + half) << 12) + ((4 * v) << 6) + X) * 2;
        e[0] = mux4(o0, g_U1[ub],       g_U1[ub + 1]);
        e[1] = mux4(o1, g_U1[ub + 128], g_U1[ub + 129]);
        e[2] = mux4(o2, g_U1[ub + 256], g_U1[ub + 257]);
        e[3] = mux4(o3, g_U1[ub + 384], g_U1[ub + 385]);
    }
    __syncthreads();
    // x junction 64->32
    fft_run<true,  NT3, 129, 1, 7, 0,    0, 6>(tile, tw, 1.0f / 64.0f);
    fft_run<false, NT3, 129, 1, 7, 4128, 1, 5>(tile, tw, 1.f);
    // y junction 64->32: inv64 halves, fwd32 segs (S=3, S=1, fused S=0 + mux2)
    fft_run<true, NT3, 1, 129, 6, 64, 1, 6>(tile, tw, 1.0f / 64.0f);
    pass4<false, NT3, 1, 129, 6, 32, 2, 5, 3, false>(tile, tw, 1.f);
    pass4<false, NT3, 1, 129, 6, 32, 2, 5, 1, false>(tile, tw, 1.f);
    for (int u = threadIdx.x; u < 4096; u += NT3) {
        int X = u & 63, seg = (u >> 6) & 3, v = u >> 8;    // v in [0,16)
        float4* e = tile + X * 129 + seg * 32 + 2 * v;
        float4 a = e[0], bb = e[1];
        float4 o0 = f4add(a, bb), o1 = f4sub(a, bb);       // w=1
        int xc2 = X >> 5, yc2 = seg & 1;
        // transposed U2: index = ((cx*2+cy)<<10) + (Yb<<5) + (X&31), Yb = 2v+k
        int ub = (((xc2 * 2 + yc2) << 10) + ((2 * v) << 5) + (X & 31)) * 2;
        e[0] = mux4(o0, g_U2[ub],      g_U2[ub + 1]);
        e[1] = mux4(o1, g_U2[ub + 64], g_U2[ub + 65]);
    }
    __syncthreads();
    // final iqft2d (32-point both axes)
    fft_run<true, NT3, 129, 1, 7, 4128, 1, 5>(tile, tw, 1.0f / 32.0f);
    fft_run<true, NT3, 1, 129, 6, 32,   2, 5>(tile, tw, 1.0f / 32.0f);
    // measurement: partial prob over (xc2, yc1, yc2)
    for (int idx = threadIdx.x; idx < 1024; idx += NT3) {
        int ya = idx & 31, xa = idx >> 5;
        float s0 = 0.f, s1 = 0.f;
        #pragma unroll
        for (int xc2 = 0; xc2 < 2; ++xc2)
            #pragma unroll
            for (int yq = 0; yq < 4; ++yq) {
                float4 v = tile[(xc2 * 32 + xa) * 129 + yq * 32 + ya];
                s0 += v.x * v.x + v.y * v.y;
                s1 += v.z * v.z + v.w * v.w;
            }
        prob[(xa * 32 + ya) * 2 + 0] = s0;
        prob[(xa * 32 + ya) * 2 + 1] = s1;
    }
    __syncthreads();
    // partial GEMV
    float acc[10];
    #pragma unroll
    for (int c = 0; c < 10; ++c) acc[c] = 0.f;
    {
        int j0 = threadIdx.x * 2;
        float2 pv = *(const float2*)(prob + j0);
        #pragma unroll
        for (int c = 0; c < 10; ++c) {
            float2 wv = *(const float2*)(W + c * 2048 + j0);
            acc[c] = fmaf(pv.x, wv.x, fmaf(pv.y, wv.y, acc[c]));
        }
    }
    #pragma unroll
    for (int c = 0; c < 10; ++c)
        #pragma unroll
        for (int o = 16; o > 0; o >>= 1)
            acc[c] += __shfl_down_sync(0xffffffffu, acc[c], o);
    const int warp = threadIdx.x >> 5, lane = threadIdx.x & 31;
    if (lane == 0)
        #pragma unroll
        for (int c = 0; c < 10; ++c) red[warp * 10 + c] = acc[c];
    __syncthreads();
    if (threadIdx.x < 10) {
        float s = 0.f;
        #pragma unroll
        for (int w = 0; w < 32; ++w) s += red[w * 10 + threadIdx.x];
        g_part[(b * 2 + xc1) * 10 + threadIdx.x] = s;
    }
}

// ---------------- combine ----------------
__global__ void pc(const float* __restrict__ bias, float* __restrict__ out) {
    int i = blockIdx.x * blockDim.x + threadIdx.x;
    if (i < 5120) {
        int b = i / 10, c = i % 10;
        out[i] = bias[c] + g_part[(b * 2) * 10 + c] + g_part[(b * 2 + 1) * 10 + c];
    }
}

// ---------------- launch ----------------
extern "C" void kernel_launch(void* const* d_in, const int* in_sizes, int n_in,
                              void* d_out, int out_size) {
    const float* images = (const float*)d_in[0];
    const float* mux0 = (const float*)d_in[1];
    const float* mux1 = (const float*)d_in[2];
    const float* mux2 = (const float*)d_in[3];
    const float* W = (const float*)d_in[4];
    const float* bias = (const float*)d_in[5];
    float* out = (float*)d_out;
    (void)in_sizes; (void)n_in; (void)out_size;

    cudaFuncSetAttribute(p35, cudaFuncAttributeMaxDynamicSharedMemorySize, P35_SMEM);

    k0<<<64, 256>>>(mux0, mux1, mux2);
    p1<<<dim3(4, 512), NT1>>>(images);
    p2<<<dim3(8, 512), NT2>>>();
    p35<<<dim3(2, 512), NT3, P35_SMEM>>>(W);
    pc<<<10, 512>>>(bias, out);
}